// round 2
// baseline (speedup 1.0000x reference)
#include <cuda_runtime.h>
#include <math.h>

#define BATCH 4
#define TSTEPS 8
#define HC 64
#define HW 4096
#define CHW (HC*HW)            // 262144
#define NB (BATCH*HC*HW)       // 1048576

// ---------------- device scratch (static, zero-initialized at load) ----------------
__device__ float g_h0[NB];
__device__ float g_c0[NB];
__device__ float g_c1[NB];
__device__ float g_m[NB];
__device__ float g_A[BATCH*192*HW];
__device__ float g_Bm[BATCH*128*HW];
__device__ float g_rc[NB], g_xm[NB];
__device__ float g_r[NB], g_z[NB], g_o[NB], g_xr[NB], g_xz[NB];
__device__ float g_gcr[NB], g_gmr[NB], g_gct[NB], g_gmt[NB];
__device__ float g_q[NB], g_k[NB];
__device__ float g_attn[BATCH*64*64];
__device__ float g_hs[BATCH*TSTEPS*HC*HW];
__device__ float g_zero[NB];   // NEVER written -> stays zero across runs

__device__ __forceinline__ float sigf(float x){ return 1.f/(1.f+expf(-x)); }

// ---------------- zero the recurrent states each launch ----------------
__global__ void tg_zero_states(){
  int i = blockIdx.x*256 + threadIdx.x;
  if (i < NB){ g_h0[i]=0.f; g_c0[i]=0.f; g_c1[i]=0.f; g_m[i]=0.f; }
}

// ---------------- generic dual-input 3x3 conv, SAME pad, stride 1 ----------------
// in = concat(in0[C0], in1[C1]) along channels. Batch strides in floats.
// Block: 128 threads, tile = 8 rows x 64 cols, 16 out channels.
// Each thread: 4 horizontal pixels x 16 out channels.
__global__ void __launch_bounds__(128) tg_conv3x3(
    const float* __restrict__ in0, int C0, long bs0,
    const float* __restrict__ in1, int C1, long bs1,
    const float* __restrict__ w, const float* __restrict__ bias,
    float* __restrict__ out, long bsOut)
{
  __shared__ float tile[10*67];
  __shared__ float ws[144];
  const int tid = threadIdx.x;
  const int b   = blockIdx.z;
  const int ocb = blockIdx.y;
  const int y0  = blockIdx.x * 8;
  const int ty  = tid >> 4;
  const int tx  = (tid & 15) << 2;
  const int Cin = C0 + C1;

  // precompute cooperative tile-load slots (660 elems: 10 rows x 66 cols halo)
  int sm_addr[6], gm_off[6];
#pragma unroll
  for (int i=0;i<6;i++){
    int idx = tid + i*128;
    if (idx < 660){
      int r = idx/66, c = idx - r*66;
      int gy = y0 - 1 + r, gx = c - 1;
      sm_addr[i] = r*67 + c;
      gm_off[i]  = (gy>=0 && gy<64 && gx>=0 && gx<64) ? gy*64+gx : -1;
    } else { sm_addr[i] = -1; gm_off[i] = -1; }
  }

  float acc[16][4];
#pragma unroll
  for (int oc=0;oc<16;oc++){
    float bv = bias[ocb*16+oc];
#pragma unroll
    for (int p=0;p<4;p++) acc[oc][p] = bv;
  }

  for (int cin=0; cin<Cin; cin++){
    const float* src = (cin < C0) ? (in0 + (long)b*bs0 + (long)cin*HW)
                                  : (in1 + (long)b*bs1 + (long)(cin-C0)*HW);
    __syncthreads();
#pragma unroll
    for (int i=0;i<6;i++)
      if (sm_addr[i] >= 0)
        tile[sm_addr[i]] = (gm_off[i] >= 0) ? src[gm_off[i]] : 0.f;
    // 144 weights loaded by 128 threads: strided (fixes R1 bug where
    // ws[128..143] were never written)
    for (int i=tid; i<144; i+=128){
      int wj = i/9, wk = i - wj*9;
      ws[i] = w[((long)(ocb*16 + wj)*Cin + cin)*9 + wk];
    }
    __syncthreads();

    float xin[3][6];
#pragma unroll
    for (int r=0;r<3;r++)
#pragma unroll
      for (int c=0;c<6;c++)
        xin[r][c] = tile[(ty+r)*67 + tx + c];

#pragma unroll
    for (int oc=0;oc<16;oc++){
      float wv[9];
#pragma unroll
      for (int k=0;k<9;k++) wv[k] = ws[oc*9+k];
#pragma unroll
      for (int p=0;p<4;p++){
        float s = acc[oc][p];
#pragma unroll
        for (int ky=0;ky<3;ky++)
#pragma unroll
          for (int kx=0;kx<3;kx++)
            s += wv[ky*3+kx]*xin[ky][p+kx];
        acc[oc][p] = s;
      }
    }
  }

  const long ob = (long)b*bsOut + (long)(ocb*16)*HW + (long)(y0+ty)*64 + tx;
#pragma unroll
  for (int oc=0;oc<16;oc++){
    float4 v = make_float4(acc[oc][0],acc[oc][1],acc[oc][2],acc[oc][3]);
    *reinterpret_cast<float4*>(&out[ob + (long)oc*HW]) = v;
  }
}

// ---------------- gate pointwise: r,z,o,xr,xz, rc=r*c, xm=xr*m ----------------
__global__ void tg_gates(
    const float* __restrict__ A, const float* __restrict__ Bm,
    const float* __restrict__ h, long hbs,
    const float* __restrict__ c,
    const float* __restrict__ tg, const float* __restrict__ tdh,
    const float* __restrict__ tdm)
{
  int idx = blockIdx.x*256 + threadIdx.x;
  if (idx >= NB) return;
  int pix = idx & (HW-1);
  int ch  = (idx >> 12) & 63;
  int b   = idx >> 18;
  float gate = sigf(tg[ch]);
  float dh = expf(-tdh[ch]);
  float dm = expf(-tdm[ch]);
  long aB = ((long)b*192 + ch)*HW + pix;
  long bB = ((long)b*128 + ch)*HW + pix;
  float hv = h[(long)b*hbs + (long)ch*HW + pix];
  float cv = c[idx];
  float mv = g_m[idx];
  float r  = sigf(A[aB]*gate + hv*dh);
  float z  = sigf(A[aB + (long)64*HW]*gate + hv*dh);
  float o  = sigf(A[aB + (long)128*HW]);
  float xr = sigf(Bm[bB]*gate + mv*dm);
  float xz = sigf(Bm[bB + (long)64*HW]*gate + mv*dm);
  g_r[idx]=r; g_z[idx]=z; g_o[idx]=o; g_xr[idx]=xr; g_xz[idx]=xz;
  g_rc[idx]=r*cv; g_xm[idx]=xr*mv;
}

// ---------------- cell update: c_new, m_new (in place), keep tanh(gc), tanh(gm) ----------------
__global__ void tg_cm(float* __restrict__ c)
{
  int idx = blockIdx.x*256 + threadIdx.x;
  if (idx >= NB) return;
  float tc = tanhf(g_gcr[idx]);
  float tm = tanhf(g_gmr[idx]);
  float zv = g_z[idx], xzv = g_xz[idx];
  c[idx]   = zv*c[idx]   + (1.f-zv)*tc;
  g_m[idx] = xzv*g_m[idx] + (1.f-xzv)*tm;
  g_gct[idx]=tc; g_gmt[idx]=tm;
}

// ---------------- 1x1 conv over concat(c,m) with fused  h = o * tanh(.) ----------------
// grid (32, BATCH, 2): 128-pixel blocks, 32 out channels per z-slice
__global__ void __launch_bounds__(128) tg_conv1x1(
    const float* __restrict__ c,
    const float* __restrict__ w, const float* __restrict__ bias,
    float* __restrict__ out, long bsOut)
{
  __shared__ float ws[32*128];
  const int tid = threadIdx.x;
  const int b   = blockIdx.y;
  const int ocg = blockIdx.z;
  for (int i=tid;i<32*128;i+=128) ws[i] = w[ocg*32*128 + i];
  __syncthreads();
  const int pix = blockIdx.x*128 + tid;
  float acc[32];
#pragma unroll
  for (int oc=0;oc<32;oc++) acc[oc] = bias[ocg*32+oc];
  const long base = (long)b*CHW + pix;
  for (int cc=0;cc<64;cc++){
    float v = c[base + (long)cc*HW];
#pragma unroll
    for (int oc=0;oc<32;oc++) acc[oc] += ws[oc*128+cc]*v;
  }
  for (int cc=0;cc<64;cc++){
    float v = g_m[base + (long)cc*HW];
#pragma unroll
    for (int oc=0;oc<32;oc++) acc[oc] += ws[oc*128+64+cc]*v;
  }
#pragma unroll
  for (int oc=0;oc<32;oc++){
    int ocf = ocg*32+oc;
    float ov = g_o[base + (long)ocf*HW];
    out[(long)b*bsOut + (long)ocf*HW + pix] = ov * tanhf(acc[oc]);
  }
}

// ---------------- q/k from final-step last-layer gates ----------------
__global__ void tg_qk()
{
  int idx = blockIdx.x*256 + threadIdx.x;
  if (idx >= NB) return;
  float rv = g_r[idx], xrv = g_xr[idx];
  g_q[idx] = 0.25f*(rv + xrv + g_c1[idx] + g_gct[idx]);
  g_k[idx] = 0.25f*(rv + xrv + g_m[idx]  + g_gmt[idx]);
}

// ---------------- attention logits + softmax: one block per (b, row i) ----------------
__global__ void tg_attn()
{
  __shared__ float qs[HW];
  __shared__ float red[2];
  __shared__ float logits[64];
  __shared__ float tmp[64];
  const int b = blockIdx.y, i = blockIdx.x, t = threadIdx.x;  // 64 threads
  const float* qrow = g_q + ((long)b*64 + i)*HW;
  for (int n=t;n<HW;n+=64) qs[n] = qrow[n];
  __syncthreads();
  for (int j=0;j<64;j++){
    const float* krow = g_k + ((long)b*64 + j)*HW;
    float s = 0.f;
    for (int n=t;n<HW;n+=64) s += qs[n]*krow[n];
#pragma unroll
    for (int off=16;off;off>>=1) s += __shfl_down_sync(0xffffffffu, s, off);
    if ((t&31)==0) red[t>>5] = s;
    __syncthreads();
    if (t==0) logits[j] = (red[0]+red[1]) * 0.015625f;  // 1/sqrt(4096)
    __syncthreads();
  }
  float xv = logits[t];
  tmp[t] = xv; __syncthreads();
  for (int s2=32; s2; s2>>=1){ if (t<s2) tmp[t] = fmaxf(tmp[t], tmp[t+s2]); __syncthreads(); }
  float mx = tmp[0]; __syncthreads();
  float e = expf(xv - mx);
  tmp[t] = e; __syncthreads();
  for (int s2=32; s2; s2>>=1){ if (t<s2) tmp[t] += tmp[t+s2]; __syncthreads(); }
  g_attn[((long)b*64+i)*64 + t] = e / tmp[0];
}

// ---------------- out[b,t,c,n] = sum_d attn[b,c,d] * hs[b,t,d,n] ----------------
__global__ void __launch_bounds__(256) tg_apply(float* __restrict__ out)
{
  __shared__ float as[64*64];
  const int b = blockIdx.z, tt = blockIdx.y;
  const int n = blockIdx.x*256 + threadIdx.x;
  for (int i=threadIdx.x;i<4096;i+=256) as[i] = g_attn[(long)b*4096 + i];
  __syncthreads();
  float acc[64];
#pragma unroll
  for (int c=0;c<64;c++) acc[c]=0.f;
  const float* v = g_hs + (((long)b*TSTEPS + tt)*64)*HW + n;
  for (int d=0; d<64; d++){
    float vv = v[(long)d*HW];
#pragma unroll
    for (int c=0;c<64;c++) acc[c] += as[c*64+d]*vv;
  }
  float* op = out + (((long)b*TSTEPS + tt)*64)*HW + n;
#pragma unroll
  for (int c=0;c<64;c++) op[(long)c*HW] = acc[c];
}

// ---------------- orchestration ----------------
extern "C" void kernel_launch(void* const* d_in, const int* in_sizes, int n_in,
                              void* d_out, int out_size)
{
  (void)in_sizes; (void)n_in; (void)out_size;
  const float* x      = (const float*)d_in[0];
  const float* w_rzo0 = (const float*)d_in[1];
  const float* b_rzo0 = (const float*)d_in[2];
  const float* w_rz0  = (const float*)d_in[3];
  const float* b_rz0  = (const float*)d_in[4];
  const float* w_h0   = (const float*)d_in[5];
  const float* b_h0   = (const float*)d_in[6];
  const float* w_o0   = (const float*)d_in[7];
  const float* b_o0   = (const float*)d_in[8];
  const float* td_h0  = (const float*)d_in[9];
  const float* td_m0  = (const float*)d_in[10];
  const float* tg0    = (const float*)d_in[11];
  const float* w_rzo1 = (const float*)d_in[12];
  const float* b_rzo1 = (const float*)d_in[13];
  const float* w_rz1  = (const float*)d_in[14];
  const float* b_rz1  = (const float*)d_in[15];
  const float* w_h1   = (const float*)d_in[16];
  const float* b_h1   = (const float*)d_in[17];
  const float* w_o1   = (const float*)d_in[18];
  const float* b_o1   = (const float*)d_in[19];
  const float* td_h1  = (const float*)d_in[20];
  const float* td_m1  = (const float*)d_in[21];
  const float* tg1    = (const float*)d_in[22];

  float *p_h0,*p_c0,*p_c1,*p_m,*p_A,*p_Bm,*p_rc,*p_xm,*p_gcr,*p_gmr,*p_hs,*p_zero;
  cudaGetSymbolAddress((void**)&p_h0,  g_h0);
  cudaGetSymbolAddress((void**)&p_c0,  g_c0);
  cudaGetSymbolAddress((void**)&p_c1,  g_c1);
  cudaGetSymbolAddress((void**)&p_m,   g_m);
  cudaGetSymbolAddress((void**)&p_A,   g_A);
  cudaGetSymbolAddress((void**)&p_Bm,  g_Bm);
  cudaGetSymbolAddress((void**)&p_rc,  g_rc);
  cudaGetSymbolAddress((void**)&p_xm,  g_xm);
  cudaGetSymbolAddress((void**)&p_gcr, g_gcr);
  cudaGetSymbolAddress((void**)&p_gmr, g_gmr);
  cudaGetSymbolAddress((void**)&p_hs,  g_hs);
  cudaGetSymbolAddress((void**)&p_zero,g_zero);

  const long nbs = (long)CHW;

  tg_zero_states<<<NB/256, 256>>>();

  for (int t=0; t<TSTEPS; t++){
    // ---------- layer 0 ----------
    const float* xt = x + (long)t*16*HW;
    const long xbs = (long)TSTEPS*16*HW;
    tg_conv3x3<<<dim3(8,12,BATCH),128>>>(xt,16,xbs, p_h0,64,nbs, w_rzo0,b_rzo0, p_A, (long)192*HW);
    tg_conv3x3<<<dim3(8, 8,BATCH),128>>>(xt,16,xbs, p_m ,64,nbs, w_rz0 ,b_rz0 , p_Bm,(long)128*HW);
    tg_gates<<<NB/256,256>>>(p_A,p_Bm, p_h0,nbs, p_c0, tg0, td_h0, td_m0);
    tg_conv3x3<<<dim3(8, 4,BATCH),128>>>(xt,16,xbs, p_rc,64,nbs, w_h0,b_h0, p_gcr, nbs);
    tg_conv3x3<<<dim3(8, 4,BATCH),128>>>(xt,16,xbs, p_xm,64,nbs, w_h0,b_h0, p_gmr, nbs);
    tg_cm<<<NB/256,256>>>(p_c0);
    tg_conv1x1<<<dim3(32,BATCH,2),128>>>(p_c0, w_o0, b_o0, p_h0, nbs);

    // ---------- layer 1 ----------
    const float* h1p = (t==0) ? p_zero : (p_hs + (long)(t-1)*CHW);
    const long h1bs  = (t==0) ? nbs : (long)TSTEPS*CHW;
    tg_conv3x3<<<dim3(8,12,BATCH),128>>>(p_h0,64,nbs, h1p,64,h1bs, w_rzo1,b_rzo1, p_A, (long)192*HW);
    tg_conv3x3<<<dim3(8, 8,BATCH),128>>>(p_h0,64,nbs, p_m,64,nbs,  w_rz1 ,b_rz1 , p_Bm,(long)128*HW);
    tg_gates<<<NB/256,256>>>(p_A,p_Bm, h1p,h1bs, p_c1, tg1, td_h1, td_m1);
    tg_conv3x3<<<dim3(8, 4,BATCH),128>>>(p_h0,64,nbs, p_rc,64,nbs, w_h1,b_h1, p_gcr, nbs);
    tg_conv3x3<<<dim3(8, 4,BATCH),128>>>(p_h0,64,nbs, p_xm,64,nbs, w_h1,b_h1, p_gmr, nbs);
    tg_cm<<<NB/256,256>>>(p_c1);
    tg_conv1x1<<<dim3(32,BATCH,2),128>>>(p_c1, w_o1, b_o1, p_hs + (long)t*CHW, (long)TSTEPS*CHW);
  }

  tg_qk<<<NB/256,256>>>();
  tg_attn<<<dim3(64,BATCH),64>>>();
  tg_apply<<<dim3(16,TSTEPS,BATCH),256>>>((float*)d_out);
}